// round 1
// baseline (speedup 1.0000x reference)
#include <cuda_runtime.h>
#include <math.h>

// Problem dims
#define BB    256     // batch
#define NA    128     // atoms / timesteps
#define INF   128     // in features
#define HH    256     // hidden
#define G3    768     // 3*H
#define VV    6       // MAX_VAL
#define OUTF  256
#define KFC   1536    // VV*HH

// ---------------- scratch (static device memory; no allocations) -------------
__device__ float g_xproj[(size_t)BB * NA * G3];   // [b, t, 768]  (b_ih folded)
__device__ float g_rnn  [(size_t)BB * NA * HH];   // [b, t, 256]  GRU outputs
__device__ float g_WhhT [(size_t)HH * G3];        // [k, gj] transposed W_hh

// ---------------- W_hh transpose: [768,256] -> [256,768] --------------------
__global__ void k_transpose_whh(const float* __restrict__ W)
{
    int i = blockIdx.x * 256 + threadIdx.x;       // over 196608
    if (i < HH * G3) {
        int k  = i / G3;
        int gj = i % G3;
        g_WhhT[i] = W[(size_t)gj * HH + k];
    }
}

// ---------------- generic fp32 NT GEMM tile params ---------------------------
// C[M,N] = A[M,K] * W[N,K]^T (+bias, +activation)
#define BM 128
#define BN 64
#define BK 16
#define TM 8
#define TN 4
// 256 threads: tx in [0,16), ty in [0,16)

// ---------------- x_proj GEMM: M=32768, N=768, K=128 -------------------------
__global__ __launch_bounds__(256, 2)
void k_gemm_xproj(const float* __restrict__ A, const float* __restrict__ W,
                  const float* __restrict__ bias)
{
    __shared__ float As[BK][BM + 4];
    __shared__ float Ws[BK][BN + 4];
    const int K = INF, N = G3;

    int tid = threadIdx.x;
    int tx = tid & 15, ty = tid >> 4;
    int m0 = blockIdx.y * BM;
    int n0 = blockIdx.x * BN;

    float acc[TM][TN];
#pragma unroll
    for (int i = 0; i < TM; i++)
#pragma unroll
        for (int j = 0; j < TN; j++) acc[i][j] = 0.f;

    for (int k0 = 0; k0 < K; k0 += BK) {
#pragma unroll
        for (int l = 0; l < 2; l++) {
            int i = tid + l * 256;              // 0..511
            int m = i >> 2, kq = i & 3;
            float4 v = *(const float4*)(A + (size_t)(m0 + m) * K + k0 + kq * 4);
            As[kq * 4 + 0][m] = v.x; As[kq * 4 + 1][m] = v.y;
            As[kq * 4 + 2][m] = v.z; As[kq * 4 + 3][m] = v.w;
        }
        {
            int n = tid >> 2, kq = tid & 3;
            float4 v = *(const float4*)(W + (size_t)(n0 + n) * K + k0 + kq * 4);
            Ws[kq * 4 + 0][n] = v.x; Ws[kq * 4 + 1][n] = v.y;
            Ws[kq * 4 + 2][n] = v.z; Ws[kq * 4 + 3][n] = v.w;
        }
        __syncthreads();
#pragma unroll
        for (int k = 0; k < BK; k++) {
            float a[TM], w[TN];
#pragma unroll
            for (int i = 0; i < TM; i++) a[i] = As[k][ty * TM + i];
#pragma unroll
            for (int j = 0; j < TN; j++) w[j] = Ws[k][tx * TN + j];
#pragma unroll
            for (int i = 0; i < TM; i++)
#pragma unroll
                for (int j = 0; j < TN; j++)
                    acc[i][j] = fmaf(a[i], w[j], acc[i][j]);
        }
        __syncthreads();
    }
#pragma unroll
    for (int i = 0; i < TM; i++) {
        int m = m0 + ty * TM + i;
        float4 o;
        int n = n0 + tx * TN;
        o.x = acc[i][0] + bias[n + 0];
        o.y = acc[i][1] + bias[n + 1];
        o.z = acc[i][2] + bias[n + 2];
        o.w = acc[i][3] + bias[n + 3];
        *(float4*)(g_xproj + (size_t)m * G3 + n) = o;
    }
}

// ---------------- FC GEMM with gathered A: M=32768, N=256, K=1536 -----------
__global__ __launch_bounds__(256, 2)
void k_gemm_fc(const int* __restrict__ bonded, const float* __restrict__ Wfc,
               const float* __restrict__ bfc, float* __restrict__ Out)
{
    __shared__ float As[BK][BM + 4];
    __shared__ float Ws[BK][BN + 4];
    __shared__ int   idx_s[BM][VV];
    const int K = KFC, N = OUTF;

    int tid = threadIdx.x;
    int tx = tid & 15, ty = tid >> 4;
    int b  = blockIdx.y;                       // one batch per block row (BM==NA)
    int n0 = blockIdx.x * BN;

    // load bonded indices for this batch: 128*6 ints
    for (int i = tid; i < BM * VV; i += 256)
        idx_s[i / VV][i % VV] = bonded[(size_t)b * NA * VV + i];
    __syncthreads();

    float acc[TM][TN];
#pragma unroll
    for (int i = 0; i < TM; i++)
#pragma unroll
        for (int j = 0; j < TN; j++) acc[i][j] = 0.f;

    for (int k0 = 0; k0 < K; k0 += BK) {
        int v   = k0 >> 8;       // BK=16 divides 256, v constant per tile
        int hh0 = k0 & 255;
#pragma unroll
        for (int l = 0; l < 2; l++) {
            int i = tid + l * 256;
            int m = i >> 2, kq = i & 3;
            int a = idx_s[m][v];
            float4 val = *(const float4*)(g_rnn + ((size_t)b * NA + a) * HH + hh0 + kq * 4);
            As[kq * 4 + 0][m] = val.x; As[kq * 4 + 1][m] = val.y;
            As[kq * 4 + 2][m] = val.z; As[kq * 4 + 3][m] = val.w;
        }
        {
            int n = tid >> 2, kq = tid & 3;
            float4 val = *(const float4*)(Wfc + (size_t)(n0 + n) * K + k0 + kq * 4);
            Ws[kq * 4 + 0][n] = val.x; Ws[kq * 4 + 1][n] = val.y;
            Ws[kq * 4 + 2][n] = val.z; Ws[kq * 4 + 3][n] = val.w;
        }
        __syncthreads();
#pragma unroll
        for (int k = 0; k < BK; k++) {
            float a[TM], w[TN];
#pragma unroll
            for (int i = 0; i < TM; i++) a[i] = As[k][ty * TM + i];
#pragma unroll
            for (int j = 0; j < TN; j++) w[j] = Ws[k][tx * TN + j];
#pragma unroll
            for (int i = 0; i < TM; i++)
#pragma unroll
                for (int j = 0; j < TN; j++)
                    acc[i][j] = fmaf(a[i], w[j], acc[i][j]);
        }
        __syncthreads();
    }
#pragma unroll
    for (int i = 0; i < TM; i++) {
        int m = b * NA + ty * TM + i;
        int n = n0 + tx * TN;
        float4 o;
        float y0 = acc[i][0] + bfc[n + 0];
        float y1 = acc[i][1] + bfc[n + 1];
        float y2 = acc[i][2] + bfc[n + 2];
        float y3 = acc[i][3] + bfc[n + 3];
        o.x = y0 >= 0.f ? y0 : 0.1f * y0;
        o.y = y1 >= 0.f ? y1 : 0.1f * y1;
        o.z = y2 >= 0.f ? y2 : 0.1f * y2;
        o.w = y3 >= 0.f ? y3 : 0.1f * y3;
        *(float4*)(Out + (size_t)m * N + n) = o;
    }
}

// ---------------- GRU step kernel --------------------------------------------
// grid: (8 j-tiles of 32, 16 batch-tiles of 16); 128 threads.
// thread: jg = tid&15 -> 2 consecutive j; bg = tid>>4 -> 2 consecutive batches.
// gh[b, g*256+j] = sum_k h[b,k] * WhhT[k, g*256+j]
__global__ __launch_bounds__(128, 4)
void k_gru_step(const float* __restrict__ bhh, int t)
{
    __shared__ float hs[256 * 17];   // hs[k*17 + local_b], padded
    __shared__ float ws[32 * 96];    // ws[kk*96 + g*32 + jj]

    int tid = threadIdx.x;
    int jg = tid & 15, bg = tid >> 4;
    int j0 = blockIdx.x * 32;
    int b0 = blockIdx.y * 16;
    int j  = j0 + jg * 2;
    int bl = bg * 2;                  // local batch base

    // stage h_prev into smem
    if (t == 0) {
        for (int i = tid; i < 256 * 17; i += 128) hs[i] = 0.f;
    } else {
        for (int i = tid; i < 4096; i += 128) {
            int kk = i & 255, b_ = i >> 8;
            hs[kk * 17 + b_] =
                g_rnn[(((size_t)(b0 + b_)) * NA + (t - 1)) * HH + kk];
        }
    }
    __syncthreads();

    float acc[3][2][2];
#pragma unroll
    for (int g = 0; g < 3; g++)
#pragma unroll
        for (int a = 0; a < 2; a++)
#pragma unroll
            for (int c = 0; c < 2; c++) acc[g][a][c] = 0.f;

    if (t > 0) {
        for (int k0 = 0; k0 < 256; k0 += 32) {
#pragma unroll
            for (int l = 0; l < 24; l++) {
                int i = tid + l * 128;        // 0..3071
                int kk = i / 96, r = i % 96;  // r = g*32 + jj
                ws[i] = g_WhhT[(size_t)(k0 + kk) * G3 + (r >> 5) * HH + j0 + (r & 31)];
            }
            __syncthreads();
#pragma unroll 8
            for (int kk = 0; kk < 32; kk++) {
                const float* wr = ws + kk * 96 + jg * 2;
                float w0a = wr[0],   w0b = wr[1];
                float w1a = wr[32],  w1b = wr[33];
                float w2a = wr[64],  w2b = wr[65];
                const float* hr = hs + (k0 + kk) * 17 + bl;
                float h0 = hr[0], h1 = hr[1];
                acc[0][0][0] = fmaf(h0, w0a, acc[0][0][0]);
                acc[0][0][1] = fmaf(h1, w0a, acc[0][0][1]);
                acc[0][1][0] = fmaf(h0, w0b, acc[0][1][0]);
                acc[0][1][1] = fmaf(h1, w0b, acc[0][1][1]);
                acc[1][0][0] = fmaf(h0, w1a, acc[1][0][0]);
                acc[1][0][1] = fmaf(h1, w1a, acc[1][0][1]);
                acc[1][1][0] = fmaf(h0, w1b, acc[1][1][0]);
                acc[1][1][1] = fmaf(h1, w1b, acc[1][1][1]);
                acc[2][0][0] = fmaf(h0, w2a, acc[2][0][0]);
                acc[2][0][1] = fmaf(h1, w2a, acc[2][0][1]);
                acc[2][1][0] = fmaf(h0, w2b, acc[2][1][0]);
                acc[2][1][1] = fmaf(h1, w2b, acc[2][1][1]);
            }
            __syncthreads();
        }
    }

    // gates + h_new
#pragma unroll
    for (int dj = 0; dj < 2; dj++) {
        int jj = j + dj;
        float br = bhh[jj], bz = bhh[256 + jj], bn = bhh[512 + jj];
#pragma unroll
        for (int db = 0; db < 2; db++) {
            int bglob = b0 + bl + db;
            size_t xb = ((size_t)bglob * NA + t) * G3 + jj;
            float xr = g_xproj[xb];
            float xz = g_xproj[xb + 256];
            float xn = g_xproj[xb + 512];
            float hrv = acc[0][dj][db] + br;
            float hzv = acc[1][dj][db] + bz;
            float hnv = acc[2][dj][db] + bn;
            float r = 1.f / (1.f + __expf(-(xr + hrv)));
            float z = 1.f / (1.f + __expf(-(xz + hzv)));
            float n = tanhf(xn + r * hnv);
            float hprev = hs[jj * 17 + bl + db];
            float hnew = (1.f - z) * n + z * hprev;
            g_rnn[((size_t)bglob * NA + t) * HH + jj] = hnew;
        }
    }
}

// ---------------- launch ------------------------------------------------------
extern "C" void kernel_launch(void* const* d_in, const int* in_sizes, int n_in,
                              void* d_out, int out_size)
{
    const float* x      = (const float*)d_in[0];
    const int*   bonded = (const int*)  d_in[1];
    const float* W_ih   = (const float*)d_in[2];
    const float* W_hh   = (const float*)d_in[3];
    const float* b_ih   = (const float*)d_in[4];
    const float* b_hh   = (const float*)d_in[5];
    const float* W_fc   = (const float*)d_in[6];
    const float* b_fc   = (const float*)d_in[7];
    float* out = (float*)d_out;

    // 1) transpose W_hh for coalesced step-kernel loads
    k_transpose_whh<<<(HH * G3 + 255) / 256, 256>>>(W_hh);

    // 2) x_proj = x @ W_ih^T + b_ih   (M=32768, N=768, K=128)
    k_gemm_xproj<<<dim3(G3 / BN, (BB * NA) / BM), 256>>>(x, W_ih, b_ih);

    // 3) GRU recurrence: 128 sequential steps
    for (int t = 0; t < NA; t++)
        k_gru_step<<<dim3(HH / 32, BB / 16), 128>>>(b_hh, t);

    // 4) gather + FC + leaky relu  (M=32768, N=256, K=1536)
    k_gemm_fc<<<dim3(OUTF / BN, BB), 256>>>(bonded, W_fc, b_fc, out);
}

// round 2
// speedup vs baseline: 1.2770x; 1.2770x over previous
#include <cuda_runtime.h>
#include <math.h>
#include <stdint.h>

// Problem dims
#define BB    256     // batch
#define NA    128     // atoms / timesteps
#define INF   128     // in features
#define HH    256     // hidden
#define G3    768     // 3*H
#define VV    6       // MAX_VAL
#define OUTF  256
#define KFC   1536    // VV*HH

// ---------------- scratch (static device memory; no allocations) -------------
__device__ float g_xproj[(size_t)BB * NA * G3];   // [b, t, 768]  (b_ih folded)
__device__ float g_rnn  [(size_t)BB * NA * HH];   // [b, t, 256]  GRU outputs

// ---------------- generic fp32 NT GEMM tile params ---------------------------
#define BM 128
#define BN 64
#define BK 16
#define TM 8
#define TN 4

// ---------------- x_proj GEMM: M=32768, N=768, K=128 -------------------------
__global__ __launch_bounds__(256, 2)
void k_gemm_xproj(const float* __restrict__ A, const float* __restrict__ W,
                  const float* __restrict__ bias)
{
    __shared__ float As[BK][BM + 4];
    __shared__ float Ws[BK][BN + 4];
    const int K = INF;

    int tid = threadIdx.x;
    int tx = tid & 15, ty = tid >> 4;
    int m0 = blockIdx.y * BM;
    int n0 = blockIdx.x * BN;

    float acc[TM][TN];
#pragma unroll
    for (int i = 0; i < TM; i++)
#pragma unroll
        for (int j = 0; j < TN; j++) acc[i][j] = 0.f;

    for (int k0 = 0; k0 < K; k0 += BK) {
#pragma unroll
        for (int l = 0; l < 2; l++) {
            int i = tid + l * 256;
            int m = i >> 2, kq = i & 3;
            float4 v = *(const float4*)(A + (size_t)(m0 + m) * K + k0 + kq * 4);
            As[kq * 4 + 0][m] = v.x; As[kq * 4 + 1][m] = v.y;
            As[kq * 4 + 2][m] = v.z; As[kq * 4 + 3][m] = v.w;
        }
        {
            int n = tid >> 2, kq = tid & 3;
            float4 v = *(const float4*)(W + (size_t)(n0 + n) * K + k0 + kq * 4);
            Ws[kq * 4 + 0][n] = v.x; Ws[kq * 4 + 1][n] = v.y;
            Ws[kq * 4 + 2][n] = v.z; Ws[kq * 4 + 3][n] = v.w;
        }
        __syncthreads();
#pragma unroll
        for (int k = 0; k < BK; k++) {
            float a[TM], w[TN];
#pragma unroll
            for (int i = 0; i < TM; i++) a[i] = As[k][ty * TM + i];
#pragma unroll
            for (int j = 0; j < TN; j++) w[j] = Ws[k][tx * TN + j];
#pragma unroll
            for (int i = 0; i < TM; i++)
#pragma unroll
                for (int j = 0; j < TN; j++)
                    acc[i][j] = fmaf(a[i], w[j], acc[i][j]);
        }
        __syncthreads();
    }
#pragma unroll
    for (int i = 0; i < TM; i++) {
        int m = m0 + ty * TM + i;
        float4 o;
        int n = n0 + tx * TN;
        o.x = acc[i][0] + bias[n + 0];
        o.y = acc[i][1] + bias[n + 1];
        o.z = acc[i][2] + bias[n + 2];
        o.w = acc[i][3] + bias[n + 3];
        *(float4*)(g_xproj + (size_t)m * G3 + n) = o;
    }
}

// ---------------- FC GEMM with gathered A: M=32768, N=256, K=1536 -----------
__global__ __launch_bounds__(256, 2)
void k_gemm_fc(const int* __restrict__ bonded, const float* __restrict__ Wfc,
               const float* __restrict__ bfc, float* __restrict__ Out)
{
    __shared__ float As[BK][BM + 4];
    __shared__ float Ws[BK][BN + 4];
    __shared__ int   idx_s[BM][VV];
    const int K = KFC, N = OUTF;

    int tid = threadIdx.x;
    int tx = tid & 15, ty = tid >> 4;
    int b  = blockIdx.y;
    int n0 = blockIdx.x * BN;

    for (int i = tid; i < BM * VV; i += 256)
        idx_s[i / VV][i % VV] = bonded[(size_t)b * NA * VV + i];
    __syncthreads();

    float acc[TM][TN];
#pragma unroll
    for (int i = 0; i < TM; i++)
#pragma unroll
        for (int j = 0; j < TN; j++) acc[i][j] = 0.f;

    for (int k0 = 0; k0 < K; k0 += BK) {
        int v   = k0 >> 8;
        int hh0 = k0 & 255;
#pragma unroll
        for (int l = 0; l < 2; l++) {
            int i = tid + l * 256;
            int m = i >> 2, kq = i & 3;
            int a = idx_s[m][v];
            float4 val = *(const float4*)(g_rnn + ((size_t)b * NA + a) * HH + hh0 + kq * 4);
            As[kq * 4 + 0][m] = val.x; As[kq * 4 + 1][m] = val.y;
            As[kq * 4 + 2][m] = val.z; As[kq * 4 + 3][m] = val.w;
        }
        {
            int n = tid >> 2, kq = tid & 3;
            float4 val = *(const float4*)(Wfc + (size_t)(n0 + n) * K + k0 + kq * 4);
            Ws[kq * 4 + 0][n] = val.x; Ws[kq * 4 + 1][n] = val.y;
            Ws[kq * 4 + 2][n] = val.z; Ws[kq * 4 + 3][n] = val.w;
        }
        __syncthreads();
#pragma unroll
        for (int k = 0; k < BK; k++) {
            float a[TM], w[TN];
#pragma unroll
            for (int i = 0; i < TM; i++) a[i] = As[k][ty * TM + i];
#pragma unroll
            for (int j = 0; j < TN; j++) w[j] = Ws[k][tx * TN + j];
#pragma unroll
            for (int i = 0; i < TM; i++)
#pragma unroll
                for (int j = 0; j < TN; j++)
                    acc[i][j] = fmaf(a[i], w[j], acc[i][j]);
        }
        __syncthreads();
    }
#pragma unroll
    for (int i = 0; i < TM; i++) {
        int m = b * NA + ty * TM + i;
        int n = n0 + tx * TN;
        float4 o;
        float y0 = acc[i][0] + bfc[n + 0];
        float y1 = acc[i][1] + bfc[n + 1];
        float y2 = acc[i][2] + bfc[n + 2];
        float y3 = acc[i][3] + bfc[n + 3];
        o.x = y0 >= 0.f ? y0 : 0.1f * y0;
        o.y = y1 >= 0.f ? y1 : 0.1f * y1;
        o.z = y2 >= 0.f ? y2 : 0.1f * y2;
        o.w = y3 >= 0.f ? y3 : 0.1f * y3;
        *(float4*)(Out + (size_t)m * N + n) = o;
    }
}

// ---------------- persistent cluster GRU -------------------------------------
// 16 clusters x 8 CTAs. Cluster c owns batches [16c, 16c+16).
// CTA rank r owns hidden slice [32r, 32r+32) (x3 gates = 96 W_hh rows in SMEM).
// h double-buffered in SMEM [2][16][256]; slices exchanged via DSMEM stores
// + one cluster.sync per step. W_hh loaded ONCE for all 128 steps.

__device__ __forceinline__ void st_cluster_f32(uint32_t laddr, uint32_t rank, float v)
{
    uint32_t raddr;
    asm volatile("mapa.shared::cluster.u32 %0, %1, %2;" : "=r"(raddr) : "r"(laddr), "r"(rank));
    asm volatile("st.shared::cluster.f32 [%0], %1;" :: "r"(raddr), "f"(v) : "memory");
}

__device__ __forceinline__ uint32_t smem_u32(const void* p)
{
    uint32_t a;
    asm("{ .reg .u64 t; cvta.to.shared.u64 t, %1; cvt.u32.u64 %0, t; }" : "=r"(a) : "l"(p));
    return a;
}

#define W_FLOATS (64 * 96 * 4)     // 24576 floats = 96KB  : Wsm[k4][row(g*32+j)][4]
#define H_FLOATS (16 * 256)        // 4096 floats per buffer
#define GRU_SMEM ((W_FLOATS + 2 * H_FLOATS) * 4)   // 131072 bytes

__global__ void __cluster_dims__(8, 1, 1) __launch_bounds__(128, 1)
k_gru_persist(const float* __restrict__ W_hh, const float* __restrict__ b_hh)
{
    extern __shared__ float sm[];
    float* Wsm = sm;                       // 24576 floats
    float* hs  = sm + W_FLOATS;            // 2 x 4096 floats

    const int tid  = threadIdx.x;
    const int lane = tid & 31;             // hidden j within slice
    const int bq   = tid >> 5;             // warp -> 4-batch group
    uint32_t rank;
    asm("mov.u32 %0, %%cluster_ctarank;" : "=r"(rank));
    const int b0   = (blockIdx.x >> 3) * 16;       // cluster batch base
    const int jglob = (int)rank * 32 + lane;       // hidden index 0..255

    // ---- load W slice once: row = g*32+j  <->  W_hh[g*256 + jglob_row][k] ----
    for (int i = tid; i < 96 * 64; i += 128) {
        int row = i >> 6, k4 = i & 63;
        int g = row >> 5, j = row & 31;
        float4 v = *(const float4*)(W_hh + ((size_t)(g * 256 + (int)rank * 32 + j)) * 256 + k4 * 4);
        float* d = Wsm + (size_t)(k4 * 96 + row) * 4;
        d[0] = v.x; d[1] = v.y; d[2] = v.z; d[3] = v.w;
    }
    // zero h buffer 0 (t=0 state)
    for (int i = tid; i < H_FLOATS; i += 128) hs[i] = 0.f;
    __syncthreads();

    const float br = b_hh[jglob], bz = b_hh[256 + jglob], bn = b_hh[512 + jglob];
    const uint32_t hs_addr = smem_u32(hs);

    for (int t = 0; t < NA; t++) {
        const float* hc = hs + (t & 1) * H_FLOATS;
        const uint32_t hn_off = ((t + 1) & 1) * H_FLOATS;

        // prefetch xproj for my 4 batches x 3 gates
        float xr[4], xz[4], xn[4];
#pragma unroll
        for (int b = 0; b < 4; b++) {
            const float* xp = g_xproj + ((size_t)(b0 + bq * 4 + b) * NA + t) * G3 + jglob;
            xr[b] = __ldg(xp);
            xz[b] = __ldg(xp + 256);
            xn[b] = __ldg(xp + 512);
        }

        float acc[4][3];
#pragma unroll
        for (int b = 0; b < 4; b++)
#pragma unroll
            for (int g = 0; g < 3; g++) acc[b][g] = 0.f;

#pragma unroll 4
        for (int k4 = 0; k4 < 64; k4++) {
            float4 wv[3];
#pragma unroll
            for (int g = 0; g < 3; g++)
                wv[g] = *(const float4*)(Wsm + (size_t)(k4 * 96 + g * 32 + lane) * 4);
#pragma unroll
            for (int b = 0; b < 4; b++) {
                float4 hv = *(const float4*)(hc + (bq * 4 + b) * 256 + k4 * 4);
#pragma unroll
                for (int g = 0; g < 3; g++) {
                    acc[b][g] = fmaf(hv.x, wv[g].x, acc[b][g]);
                    acc[b][g] = fmaf(hv.y, wv[g].y, acc[b][g]);
                    acc[b][g] = fmaf(hv.z, wv[g].z, acc[b][g]);
                    acc[b][g] = fmaf(hv.w, wv[g].w, acc[b][g]);
                }
            }
        }

        // gates + h_new + exchange
#pragma unroll
        for (int b = 0; b < 4; b++) {
            float r = 1.f / (1.f + __expf(-(xr[b] + acc[b][0] + br)));
            float z = 1.f / (1.f + __expf(-(xz[b] + acc[b][1] + bz)));
            float n = tanhf(xn[b] + r * (acc[b][2] + bn));
            float hp = hc[(bq * 4 + b) * 256 + jglob];
            float hv2 = (1.f - z) * n + z * hp;

            g_rnn[((size_t)(b0 + bq * 4 + b) * NA + t) * HH + jglob] = hv2;

            uint32_t laddr = hs_addr + (hn_off + (bq * 4 + b) * 256 + jglob) * 4;
#pragma unroll
            for (uint32_t c = 0; c < 8; c++) st_cluster_f32(laddr, c, hv2);
        }

        // one cluster barrier per step (release/acquire orders DSMEM stores)
        asm volatile("barrier.cluster.arrive.aligned;" ::: "memory");
        asm volatile("barrier.cluster.wait.aligned;" ::: "memory");
    }
}

// ---------------- launch ------------------------------------------------------
extern "C" void kernel_launch(void* const* d_in, const int* in_sizes, int n_in,
                              void* d_out, int out_size)
{
    const float* x      = (const float*)d_in[0];
    const int*   bonded = (const int*)  d_in[1];
    const float* W_ih   = (const float*)d_in[2];
    const float* W_hh   = (const float*)d_in[3];
    const float* b_ih   = (const float*)d_in[4];
    const float* b_hh   = (const float*)d_in[5];
    const float* W_fc   = (const float*)d_in[6];
    const float* b_fc   = (const float*)d_in[7];
    float* out = (float*)d_out;

    cudaFuncSetAttribute(k_gru_persist,
                         cudaFuncAttributeMaxDynamicSharedMemorySize, GRU_SMEM);

    // 1) x_proj = x @ W_ih^T + b_ih   (M=32768, N=768, K=128)
    k_gemm_xproj<<<dim3(G3 / BN, (BB * NA) / BM), 256>>>(x, W_ih, b_ih);

    // 2) GRU: one persistent kernel, 16 clusters x 8 CTAs, W resident in SMEM
    k_gru_persist<<<128, 128, GRU_SMEM>>>(W_hh, b_hh);

    // 3) gather + FC + leaky relu  (M=32768, N=256, K=1536)
    k_gemm_fc<<<dim3(OUTF / BN, BB), 256>>>(bonded, W_fc, b_fc, out);
}